// round 1
// baseline (speedup 1.0000x reference)
#include <cuda_runtime.h>
#include <math.h>

// Problem constants
#define BB   64
#define TT   512
#define HH   512
#define KG   10
#define NC   80
#define UU   64

#define NBLK 128
#define NTHR 256

// padded K dimension of the fused recurrent GEMM:
//  [0,80)   : w  (W_ih cols 3..83)
//  [80,83)  : x  (W_ih cols 0..3)
//  [83]     : zero pad
//  [84,596) : h  (W_hh cols 0..512)
//  [596,612): zero pad
#define KP    612
#define NCH4  153      // KP/4 float4 chunks per row
#define WOFF  0
#define XOFF  80
#define HOFF  84
#define GSTR  65       // gbuf stride (16 gate rows x 64 batch, padded)

#define SMEM_FLOATS (16*KP + BB*KP + 16*GSTR)
#define SMEM_BYTES  (SMEM_FLOATS * 4)

// ---------------- grid barrier (all 128 blocks resident) ----------------
__device__ unsigned g_bar_count = 0;
__device__ volatile unsigned g_bar_gen = 0;

__device__ __forceinline__ void grid_sync() {
    __threadfence();
    __syncthreads();
    if (threadIdx.x == 0) {
        unsigned gen = g_bar_gen;
        if (atomicAdd(&g_bar_count, 1u) == (unsigned)(NBLK - 1)) {
            g_bar_count = 0;
            __threadfence();
            g_bar_gen = gen + 1;
        } else {
            while (g_bar_gen == gen) { }
            __threadfence();
        }
    }
    __syncthreads();
}

__device__ __forceinline__ float sigmoidf_acc(float x) {
    return 1.0f / (1.0f + expf(-x));
}

// ---------------- persistent kernel ----------------
__global__ __launch_bounds__(NTHR, 1)
void lstm_attn_kernel(const float* __restrict__ strokes,   // [B,T,3]
                      const int*   __restrict__ sents,     // [B,U]
                      const float* __restrict__ smask,     // [B,U]
                      const float* __restrict__ W_ih,      // [2048,83]
                      const float* __restrict__ W_hh,      // [2048,512]
                      const float* __restrict__ b_ih,      // [2048]
                      const float* __restrict__ b_hh,      // [2048]
                      const float* __restrict__ W_win,     // [30,512]
                      const float* __restrict__ b_win,     // [30]
                      float* __restrict__ out)
{
    extern __shared__ float sm[];
    float* Wsh  = sm;                 // 16 * KP  (this block's gate-row weights)
    float* inp  = Wsh + 16 * KP;      // BB * KP  (staged step input, all batches)
    float* gbuf = inp + BB * KP;      // 16 * GSTR (gates; reused as h-stage in phase 2)

    __shared__ float bias_sh[16];
    __shared__ float psh[30];
    __shared__ float alpha_sh[KG], beta_sh[KG], kap_sh[KG];
    __shared__ float phi_sh[UU];
    __shared__ int   ssh[UU];
    __shared__ float msh[UU];

    const int tid = threadIdx.x;
    const int blk = blockIdx.x;
    const int hc0 = blk * 4;          // this block's 4 h-columns

    float* hs_out = out;                               // [B,T,H]
    float* ws_out = out + (size_t)BB * TT * HH;        // [B,T,NC]

    // ---- load this block's weight slice into smem (once) ----
    for (int e = tid; e < 16 * KP; e += NTHR) {
        int j = e / KP;
        int k = e - j * KP;
        int row = (j >> 2) * HH + hc0 + (j & 3);       // q*512 + hcol
        float v = 0.0f;
        if (k < 80)                      v = W_ih[row * 83 + 3 + k];     // w part
        else if (k < 83)                 v = W_ih[row * 83 + (k - 80)];  // x part
        else if (k >= HOFF && k < HOFF + HH) v = W_hh[row * HH + (k - HOFF)];
        Wsh[e] = v;
    }
    if (tid < 16) {
        int row = (tid >> 2) * HH + hc0 + (tid & 3);
        bias_sh[tid] = b_ih[row] + b_hh[row];
    }
    if (tid < KG) kap_sh[tid] = 0.0f;
    // phase-2 blocks: load their sentence + mask once (constant over t)
    if (blk < BB && tid < UU) {
        ssh[tid] = sents[blk * UU + tid];
        msh[tid] = smask[blk * UU + tid];
    }

    // gate-GEMM thread mapping: 4b x 4j tile, k split across 4 threads
    const int ks      = tid & 3;
    const int cluster = tid >> 2;          // 0..63
    const int b0 = (cluster & 15) * 4;     // batch tile
    const int j0 = (cluster >> 4) * 4;     // gate-row tile (of 16)
    // cell-update mapping (fixed across steps -> c lives in a register)
    const int ub  = tid >> 2;              // batch
    const int ujl = tid & 3;               // local h column
    float c_state = 0.0f;

    __syncthreads();

    for (int t = 0; t < TT; ++t) {
        // ================= stage inputs [BB x KP] into smem =================
        {
            float4* inp4 = (float4*)inp;   // row stride = NCH4 float4s
            for (int idx = tid; idx < BB * NCH4; idx += NTHR) {
                int b = idx / NCH4;
                int c = idx - b * NCH4;
                float4 v = make_float4(0.f, 0.f, 0.f, 0.f);
                if (c < 20) {                               // w_prev
                    if (t > 0)
                        v = __ldcg((const float4*)(ws_out + ((size_t)b * TT + (t - 1)) * NC + c * 4));
                } else if (c == 20) {                       // x_t (+1 zero pad)
                    const float* xp = strokes + ((size_t)b * TT + t) * 3;
                    v.x = xp[0]; v.y = xp[1]; v.z = xp[2]; v.w = 0.f;
                } else if (c < 149) {                       // h_prev
                    if (t > 0)
                        v = __ldcg((const float4*)(hs_out + ((size_t)b * TT + (t - 1)) * HH + (c - 21) * 4));
                }                                           // else: zero pad
                inp4[b * NCH4 + c] = v;
            }
        }
        __syncthreads();

        // ================= gates: 64x16 GEMM over KP =================
        {
            float acc[4][4];
            #pragma unroll
            for (int i = 0; i < 4; ++i)
                #pragma unroll
                for (int j = 0; j < 4; ++j) acc[i][j] = 0.0f;

            const float4* w0 = (const float4*)(Wsh + (j0 + 0) * KP);
            const float4* w1 = (const float4*)(Wsh + (j0 + 1) * KP);
            const float4* w2 = (const float4*)(Wsh + (j0 + 2) * KP);
            const float4* w3 = (const float4*)(Wsh + (j0 + 3) * KP);
            const float4* i0 = (const float4*)(inp + (b0 + 0) * KP);
            const float4* i1 = (const float4*)(inp + (b0 + 1) * KP);
            const float4* i2 = (const float4*)(inp + (b0 + 2) * KP);
            const float4* i3 = (const float4*)(inp + (b0 + 3) * KP);

            #pragma unroll 1
            for (int c = ks; c < NCH4; c += 4) {
                float4 wv[4], iv[4];
                wv[0] = w0[c]; wv[1] = w1[c]; wv[2] = w2[c]; wv[3] = w3[c];
                iv[0] = i0[c]; iv[1] = i1[c]; iv[2] = i2[c]; iv[3] = i3[c];
                #pragma unroll
                for (int i = 0; i < 4; ++i) {
                    #pragma unroll
                    for (int j = 0; j < 4; ++j) {
                        acc[i][j] = fmaf(iv[i].x, wv[j].x, acc[i][j]);
                        acc[i][j] = fmaf(iv[i].y, wv[j].y, acc[i][j]);
                        acc[i][j] = fmaf(iv[i].z, wv[j].z, acc[i][j]);
                        acc[i][j] = fmaf(iv[i].w, wv[j].w, acc[i][j]);
                    }
                }
            }
            // reduce over the 4 k-split threads (lanes differ in bits 0..1)
            #pragma unroll
            for (int i = 0; i < 4; ++i) {
                #pragma unroll
                for (int j = 0; j < 4; ++j) {
                    float a = acc[i][j];
                    a += __shfl_xor_sync(0xffffffffu, a, 1);
                    a += __shfl_xor_sync(0xffffffffu, a, 2);
                    if (ks == 0) gbuf[(j0 + j) * GSTR + (b0 + i)] = a;
                }
            }
        }
        __syncthreads();

        // ================= LSTM cell update (one (b, col) per thread) =================
        {
            float gi = gbuf[(0 * 4 + ujl) * GSTR + ub] + bias_sh[ujl];
            float gf = gbuf[(1 * 4 + ujl) * GSTR + ub] + bias_sh[4 + ujl];
            float gg = gbuf[(2 * 4 + ujl) * GSTR + ub] + bias_sh[8 + ujl];
            float go = gbuf[(3 * 4 + ujl) * GSTR + ub] + bias_sh[12 + ujl];
            float si = sigmoidf_acc(gi);
            float sf = sigmoidf_acc(gf);
            float so = sigmoidf_acc(go);
            c_state = sf * c_state + si * tanhf(gg);
            float h = so * tanhf(c_state);
            hs_out[((size_t)ub * TT + t) * HH + hc0 + ujl] = h;
        }

        grid_sync();   // h[t] fully visible

        // ================= phase 2: attention window (block b < BB) =================
        if (blk < BB) {
            const int b = blk;
            // stage full h[b] into gbuf (reused; gate values already consumed)
            for (int m = tid; m < HH; m += NTHR)
                gbuf[m] = __ldcg(hs_out + ((size_t)b * TT + t) * HH + m);
            __syncthreads();

            // p[30] = h @ W_win.T + b_win  (8 threads per output, float4 inner)
            {
                int j = tid >> 3;          // 0..31 (30 real)
                int seg = tid & 7;
                float part = 0.0f;
                if (j < 30) {
                    const float4* wr = (const float4*)(W_win + j * HH + seg * 64);
                    const float4* hr = (const float4*)(gbuf + seg * 64);
                    #pragma unroll
                    for (int m = 0; m < 16; ++m) {
                        float4 wv = wr[m];
                        float4 hv = hr[m];
                        part = fmaf(hv.x, wv.x, part);
                        part = fmaf(hv.y, wv.y, part);
                        part = fmaf(hv.z, wv.z, part);
                        part = fmaf(hv.w, wv.w, part);
                    }
                }
                part += __shfl_down_sync(0xffffffffu, part, 4, 8);
                part += __shfl_down_sync(0xffffffffu, part, 2, 8);
                part += __shfl_down_sync(0xffffffffu, part, 1, 8);
                if (seg == 0 && j < 30) psh[j] = part + b_win[j];
            }
            __syncthreads();

            if (tid < KG) {
                alpha_sh[tid] = expf(psh[tid]);
                beta_sh[tid]  = expf(psh[10 + tid]);
                kap_sh[tid]  += expf(psh[20 + tid]);   // persistent kappa state
            }
            __syncthreads();

            // phi[u], pre-masked
            if (tid < UU) {
                float uu = (float)tid;
                float ph = 0.0f;
                #pragma unroll
                for (int k = 0; k < KG; ++k) {
                    float d = kap_sh[k] - uu;
                    ph += alpha_sh[k] * expf(-beta_sh[k] * d * d);
                }
                phi_sh[tid] = ph * msh[tid];
            }
            __syncthreads();

            // w[n] = sum_u phi[u] * onehot(sent[u])[n]  (deterministic gather)
            if (tid < NC) {
                float acc = 0.0f;
                #pragma unroll 8
                for (int u = 0; u < UU; ++u)
                    acc += (ssh[u] == tid) ? phi_sh[u] : 0.0f;
                ws_out[((size_t)b * TT + t) * NC + tid] = acc;
            }
        }

        grid_sync();   // w[t] fully visible for step t+1
    }
}

// ---------------- launch ----------------
extern "C" void kernel_launch(void* const* d_in, const int* in_sizes, int n_in,
                              void* d_out, int out_size) {
    const float* strokes = (const float*)d_in[0];
    const int*   sents   = (const int*)  d_in[1];
    const float* smaskp  = (const float*)d_in[2];
    const float* W_ih    = (const float*)d_in[3];
    const float* W_hh    = (const float*)d_in[4];
    const float* b_ih    = (const float*)d_in[5];
    const float* b_hh    = (const float*)d_in[6];
    const float* W_win   = (const float*)d_in[7];
    const float* b_win   = (const float*)d_in[8];
    float* out = (float*)d_out;

    cudaFuncSetAttribute(lstm_attn_kernel,
                         cudaFuncAttributeMaxDynamicSharedMemorySize, SMEM_BYTES);

    lstm_attn_kernel<<<NBLK, NTHR, SMEM_BYTES>>>(
        strokes, sents, smaskp, W_ih, W_hh, b_ih, b_hh, W_win, b_win, out);
}

// round 2
// speedup vs baseline: 1.4827x; 1.4827x over previous
#include <cuda_runtime.h>
#include <math.h>

// Problem constants
#define BB   64
#define TT   512
#define HH   512
#define KG   10
#define NC   80
#define UU   64

#define NBLK 128
#define NTHR 512

// padded K dimension of the fused recurrent GEMM:
//  [0,80)   : w  (W_ih cols 3..83)
//  [80,83)  : x  (W_ih cols 0..3)
//  [83]     : zero pad
//  [84,596) : h  (W_hh cols 0..512)
//  [596,612): zero pad
#define KP    612
#define NCH4  153      // KP/4 float4 chunks per row
#define HOFF  84
#define HCH0  21       // first float4 chunk of the h region (84/4)
#define GSTR  65       // gbuf stride (16 gate rows x 64 batch, padded)

#define SMEM_FLOATS (16*KP + BB*KP + 16*GSTR)
#define SMEM_BYTES  (SMEM_FLOATS * 4)

// ---------------- grid barrier (all 128 blocks resident) ----------------
__device__ unsigned g_bar_count = 0;
__device__ volatile unsigned g_bar_gen = 0;

__device__ __forceinline__ void grid_sync() {
    __threadfence();
    __syncthreads();
    if (threadIdx.x == 0) {
        unsigned gen = g_bar_gen;
        if (atomicAdd(&g_bar_count, 1u) == (unsigned)(NBLK - 1)) {
            g_bar_count = 0;
            __threadfence();
            g_bar_gen = gen + 1;
        } else {
            while (g_bar_gen == gen) { }
            __threadfence();
        }
    }
    __syncthreads();
}

__device__ __forceinline__ float sigmoidf_acc(float x) {
    return 1.0f / (1.0f + expf(-x));
}

// ---------------- persistent kernel ----------------
__global__ __launch_bounds__(NTHR, 1)
void lstm_attn_kernel(const float* __restrict__ strokes,   // [B,T,3]
                      const int*   __restrict__ sents,     // [B,U]
                      const float* __restrict__ smask,     // [B,U]
                      const float* __restrict__ W_ih,      // [2048,83]
                      const float* __restrict__ W_hh,      // [2048,512]
                      const float* __restrict__ b_ih,      // [2048]
                      const float* __restrict__ b_hh,      // [2048]
                      const float* __restrict__ W_win,     // [30,512]
                      const float* __restrict__ b_win,     // [30]
                      float* __restrict__ out)
{
    extern __shared__ float sm[];
    float* Wsh  = sm;                 // 16 * KP  (this block's gate-row weights)
    float* inp  = Wsh + 16 * KP;      // BB * KP  (staged step input, all batches)
    float* gbuf = inp + BB * KP;      // 16 * GSTR (gates)

    __shared__ float bias_sh[16];
    __shared__ float psh[32];
    __shared__ float alpha_sh[KG], beta_sh[KG], kap_sh[KG];
    __shared__ float phi_sh[UU];
    __shared__ int   ssh[UU];
    __shared__ float msh[UU];

    const int tid = threadIdx.x;
    const int blk = blockIdx.x;
    const int hc0 = blk * 4;          // this block's 4 h-columns

    float* hs_out = out;                               // [B,T,H]
    float* ws_out = out + (size_t)BB * TT * HH;        // [B,T,NC]

    // ---- load this block's weight slice into smem (once) ----
    for (int e = tid; e < 16 * KP; e += NTHR) {
        int j = e / KP;
        int k = e - j * KP;
        int row = (j >> 2) * HH + hc0 + (j & 3);       // q*512 + hcol
        float v = 0.0f;
        if (k < 80)                      v = W_ih[row * 83 + 3 + k];     // w part
        else if (k < 83)                 v = W_ih[row * 83 + (k - 80)];  // x part
        else if (k >= HOFF && k < HOFF + HH) v = W_hh[row * HH + (k - HOFF)];
        Wsh[e] = v;
    }
    if (tid < 16) {
        int row = (tid >> 2) * HH + hc0 + (tid & 3);
        bias_sh[tid] = b_ih[row] + b_hh[row];
    }
    if (tid < KG) kap_sh[tid] = 0.0f;
    if (blk < BB && tid < UU) {
        ssh[tid] = sents[blk * UU + tid];
        msh[tid] = smask[blk * UU + tid];
    }

    // ---- zero-init the whole input tile, then stage x(0) ----
    {
        float4* inp4 = (float4*)inp;
        float4 z = make_float4(0.f, 0.f, 0.f, 0.f);
        for (int idx = tid; idx < BB * NCH4; idx += NTHR) {
            int b = idx / NCH4;
            int c = idx - b * NCH4;
            inp4[b * NCH4 + c] = z;
        }
        __syncthreads();
        if (tid < BB) {
            const float* xp = strokes + (size_t)tid * TT * 3;
            inp4[tid * NCH4 + 20] = make_float4(xp[0], xp[1], xp[2], 0.f);
        }
    }

    // gate-GEMM thread mapping: 4b x 4j tile, k split across 8 threads
    const int ks      = tid & 7;
    const int cluster = tid >> 3;          // 0..63
    const int b0 = (cluster & 15) * 4;     // batch tile
    const int j0 = (cluster >> 4) * 4;     // gate-row tile (of 16)
    // cell-update mapping (threads 0..255; fixed across steps -> c in register)
    const int ub  = tid >> 2;              // batch (valid for tid<256)
    const int ujl = tid & 3;               // local h column
    float c_state = 0.0f;

    __syncthreads();

    for (int t = 0; t < TT; ++t) {
        // ======== stage w(t-1) part only (h + x already staged last step) ========
        if (t > 0) {
            float4* inp4 = (float4*)inp;
            for (int idx = tid; idx < BB * 20; idx += NTHR) {
                int b = idx / 20;
                int c = idx - b * 20;
                inp4[b * NCH4 + c] =
                    __ldcg((const float4*)(ws_out + ((size_t)b * TT + (t - 1)) * NC + c * 4));
            }
        }
        __syncthreads();

        // ================= gates: 64x16 GEMM over KP =================
        {
            float acc[4][4];
            #pragma unroll
            for (int i = 0; i < 4; ++i)
                #pragma unroll
                for (int j = 0; j < 4; ++j) acc[i][j] = 0.0f;

            const float4* w0 = (const float4*)(Wsh + (j0 + 0) * KP);
            const float4* w1 = (const float4*)(Wsh + (j0 + 1) * KP);
            const float4* w2 = (const float4*)(Wsh + (j0 + 2) * KP);
            const float4* w3 = (const float4*)(Wsh + (j0 + 3) * KP);
            const float4* i0 = (const float4*)(inp + (b0 + 0) * KP);
            const float4* i1 = (const float4*)(inp + (b0 + 1) * KP);
            const float4* i2 = (const float4*)(inp + (b0 + 2) * KP);
            const float4* i3 = (const float4*)(inp + (b0 + 3) * KP);

            #pragma unroll 1
            for (int c = ks; c < NCH4; c += 8) {
                float4 wv[4], iv[4];
                wv[0] = w0[c]; wv[1] = w1[c]; wv[2] = w2[c]; wv[3] = w3[c];
                iv[0] = i0[c]; iv[1] = i1[c]; iv[2] = i2[c]; iv[3] = i3[c];
                #pragma unroll
                for (int i = 0; i < 4; ++i) {
                    #pragma unroll
                    for (int j = 0; j < 4; ++j) {
                        acc[i][j] = fmaf(iv[i].x, wv[j].x, acc[i][j]);
                        acc[i][j] = fmaf(iv[i].y, wv[j].y, acc[i][j]);
                        acc[i][j] = fmaf(iv[i].z, wv[j].z, acc[i][j]);
                        acc[i][j] = fmaf(iv[i].w, wv[j].w, acc[i][j]);
                    }
                }
            }
            // reduce over the 8 k-split threads (lanes differ in bits 0..2)
            #pragma unroll
            for (int i = 0; i < 4; ++i) {
                #pragma unroll
                for (int j = 0; j < 4; ++j) {
                    float a = acc[i][j];
                    a += __shfl_xor_sync(0xffffffffu, a, 1);
                    a += __shfl_xor_sync(0xffffffffu, a, 2);
                    a += __shfl_xor_sync(0xffffffffu, a, 4);
                    if (ks == 0) gbuf[(j0 + j) * GSTR + (b0 + i)] = a;
                }
            }
        }
        __syncthreads();

        // ============ LSTM cell update (threads 0..255, one (b,col) each) ============
        if (tid < 256) {
            float gi = gbuf[(0 * 4 + ujl) * GSTR + ub] + bias_sh[ujl];
            float gf = gbuf[(1 * 4 + ujl) * GSTR + ub] + bias_sh[4 + ujl];
            float gg = gbuf[(2 * 4 + ujl) * GSTR + ub] + bias_sh[8 + ujl];
            float go = gbuf[(3 * 4 + ujl) * GSTR + ub] + bias_sh[12 + ujl];
            float si = sigmoidf_acc(gi);
            float sf = sigmoidf_acc(gf);
            float so = sigmoidf_acc(go);
            c_state = sf * c_state + si * tanhf(gg);
            float h = so * tanhf(c_state);
            hs_out[((size_t)ub * TT + t) * HH + hc0 + ujl] = h;
        }

        grid_sync();   // h(t) fully visible

        // ======== stage h(t) + x(t+1) for the NEXT step (all blocks) ========
        {
            float4* inp4 = (float4*)inp;
            // h region: 64 batches x 128 chunks (power-of-2 index math)
            for (int idx = tid; idx < BB * 128; idx += NTHR) {
                int b = idx >> 7;
                int c = idx & 127;
                inp4[b * NCH4 + HCH0 + c] =
                    __ldcg((const float4*)(hs_out + ((size_t)b * TT + t) * HH + c * 4));
            }
            // x(t+1) (clamped at the last step; value unused then)
            if (tid < BB) {
                int tn = (t + 1 < TT) ? (t + 1) : (TT - 1);
                const float* xp = strokes + ((size_t)tid * TT + tn) * 3;
                inp4[tid * NCH4 + 20] = make_float4(xp[0], xp[1], xp[2], 0.f);
            }
        }
        __syncthreads();

        // ================= phase 2: attention window (block b < BB) =================
        if (blk < BB) {
            const int b = blk;
            const float* hrow = inp + b * KP + HOFF;   // freshly staged h(t)[b]

            // p[30] = h @ W_win.T + b_win  (16 threads per output, float4 inner)
            {
                int j = tid >> 4;          // 0..31 (30 real)
                int seg = tid & 15;
                float part = 0.0f;
                if (j < 30) {
                    const float4* wr = (const float4*)(W_win + j * HH + seg * 32);
                    const float4* hr = (const float4*)(hrow + seg * 32);
                    #pragma unroll
                    for (int m = 0; m < 8; ++m) {
                        float4 wv = wr[m];
                        float4 hv = hr[m];
                        part = fmaf(hv.x, wv.x, part);
                        part = fmaf(hv.y, wv.y, part);
                        part = fmaf(hv.z, wv.z, part);
                        part = fmaf(hv.w, wv.w, part);
                    }
                }
                part += __shfl_down_sync(0xffffffffu, part, 8, 16);
                part += __shfl_down_sync(0xffffffffu, part, 4, 16);
                part += __shfl_down_sync(0xffffffffu, part, 2, 16);
                part += __shfl_down_sync(0xffffffffu, part, 1, 16);
                if (seg == 0 && j < 30) psh[j] = part + b_win[j];
            }
            __syncthreads();

            if (tid < KG) {
                alpha_sh[tid] = expf(psh[tid]);
                beta_sh[tid]  = expf(psh[10 + tid]);
                kap_sh[tid]  += expf(psh[20 + tid]);   // persistent kappa state
            }
            __syncthreads();

            // phi[u], pre-masked
            if (tid < UU) {
                float uu = (float)tid;
                float ph = 0.0f;
                #pragma unroll
                for (int k = 0; k < KG; ++k) {
                    float d = kap_sh[k] - uu;
                    ph += alpha_sh[k] * expf(-beta_sh[k] * d * d);
                }
                phi_sh[tid] = ph * msh[tid];
            }
            __syncthreads();

            // w[n] = sum_u phi[u] * onehot(sent[u])[n]  (deterministic gather)
            if (tid < NC) {
                float acc = 0.0f;
                #pragma unroll 8
                for (int u = 0; u < UU; ++u)
                    acc += (ssh[u] == tid) ? phi_sh[u] : 0.0f;
                ws_out[((size_t)b * TT + t) * NC + tid] = acc;
            }
        }

        grid_sync();   // w(t) fully visible for step t+1
    }
}

// ---------------- launch ----------------
extern "C" void kernel_launch(void* const* d_in, const int* in_sizes, int n_in,
                              void* d_out, int out_size) {
    const float* strokes = (const float*)d_in[0];
    const int*   sents   = (const int*)  d_in[1];
    const float* smaskp  = (const float*)d_in[2];
    const float* W_ih    = (const float*)d_in[3];
    const float* W_hh    = (const float*)d_in[4];
    const float* b_ih    = (const float*)d_in[5];
    const float* b_hh    = (const float*)d_in[6];
    const float* W_win   = (const float*)d_in[7];
    const float* b_win   = (const float*)d_in[8];
    float* out = (float*)d_out;

    cudaFuncSetAttribute(lstm_attn_kernel,
                         cudaFuncAttributeMaxDynamicSharedMemorySize, SMEM_BYTES);

    lstm_attn_kernel<<<NBLK, NTHR, SMEM_BYTES>>>(
        strokes, sents, smaskp, W_ih, W_hh, b_ih, b_hh, W_win, b_win, out);
}

// round 3
// speedup vs baseline: 1.7114x; 1.1542x over previous
#include <cuda_runtime.h>
#include <math.h>

// Problem constants
#define BB   64
#define TT   512
#define HH   512
#define KG   10
#define NC   80
#define UU   64

#define NBLK 128
#define NTHR 512
#define NGRP 4
#define GBLK 32      // blocks per group
#define BPG  16      // batches per group
#define RPB  64      // gate rows per block (16 h-cols x 4 gates)
#define CPB  16      // h columns per block

// padded K dimension of the fused recurrent GEMM:
//  [0,80)   : w  (W_ih cols 3..83)
//  [80,83)  : x  (W_ih cols 0..3)
//  [83]     : zero pad
//  [84,596) : h  (W_hh cols 0..512)
//  [596,612): zero pad
#define KP    612
#define NCH4  153     // KP/4 float4 chunks per row
#define HOFF  84
#define HCH0  21      // first float4 chunk of h region
#define GSTR  17      // gbuf row stride (16 batches + pad)

#define SMEM_FLOATS (RPB*KP + BPG*KP + RPB*GSTR)
#define SMEM_BYTES  (SMEM_FLOATS * 4)

// ---------------- per-group grid barrier (32 blocks each) ----------------
__device__ unsigned g_bar_count[NGRP] = {0, 0, 0, 0};
__device__ volatile unsigned g_bar_gen[NGRP] = {0, 0, 0, 0};

__device__ __forceinline__ void group_sync(int grp) {
    __threadfence();
    __syncthreads();
    if (threadIdx.x == 0) {
        unsigned gen = g_bar_gen[grp];
        if (atomicAdd(&g_bar_count[grp], 1u) == (unsigned)(GBLK - 1)) {
            g_bar_count[grp] = 0;
            __threadfence();
            g_bar_gen[grp] = gen + 1;
        } else {
            while (g_bar_gen[grp] == gen) { }
            __threadfence();
        }
    }
    __syncthreads();
}

__device__ __forceinline__ float sigmoidf_acc(float x) {
    return 1.0f / (1.0f + expf(-x));
}

// ---------------- persistent kernel ----------------
__global__ __launch_bounds__(NTHR, 1)
void lstm_attn_kernel(const float* __restrict__ strokes,   // [B,T,3]
                      const int*   __restrict__ sents,     // [B,U]
                      const float* __restrict__ smask,     // [B,U]
                      const float* __restrict__ W_ih,      // [2048,83]
                      const float* __restrict__ W_hh,      // [2048,512]
                      const float* __restrict__ b_ih,      // [2048]
                      const float* __restrict__ b_hh,      // [2048]
                      const float* __restrict__ W_win,     // [30,512]
                      const float* __restrict__ b_win,     // [30]
                      float* __restrict__ out)
{
    extern __shared__ float sm[];
    float* Wsh  = sm;                 // RPB * KP   (this block's 64 gate rows)
    float* inp  = Wsh + RPB * KP;     // BPG * KP   (staged input, group's 16 batches)
    float* gbuf = inp + BPG * KP;     // RPB * GSTR (gates)

    __shared__ float bias_sh[RPB];
    __shared__ float psh[32];
    __shared__ float alpha_sh[KG], beta_sh[KG], kap_sh[KG];
    __shared__ float phi_sh[UU];
    __shared__ int   ssh[UU];
    __shared__ float msh[UU];

    const int tid  = threadIdx.x;
    const int blk  = blockIdx.x;
    const int grp  = blk >> 5;        // group 0..3 -> batches [grp*16, grp*16+16)
    const int blkl = blk & 31;        // block within group
    const int hc0  = blkl * CPB;      // this block's 16 h-columns
    const int gb0  = grp * BPG;       // first global batch of group

    float* hs_out = out;                               // [B,T,H]
    float* ws_out = out + (size_t)BB * TT * HH;        // [B,T,NC]

    // ---- load this block's 64-row weight slice into smem (once) ----
    for (int e = tid; e < RPB * KP; e += NTHR) {
        int j = e / KP;                               // local gate row 0..63
        int k = e - j * KP;
        int row = (j >> 4) * HH + hc0 + (j & 15);     // q*512 + hcol
        float v = 0.0f;
        if (k < 80)                      v = W_ih[row * 83 + 3 + k];     // w part
        else if (k < 83)                 v = W_ih[row * 83 + (k - 80)];  // x part
        else if (k >= HOFF && k < HOFF + HH) v = W_hh[row * HH + (k - HOFF)];
        Wsh[e] = v;
    }
    if (tid < RPB) {
        int row = (tid >> 4) * HH + hc0 + (tid & 15);
        bias_sh[tid] = b_ih[row] + b_hh[row];
    }
    if (tid < KG) kap_sh[tid] = 0.0f;
    if (blkl < BPG && tid < UU) {          // window block for batch gb0+blkl
        ssh[tid] = sents[(gb0 + blkl) * UU + tid];
        msh[tid] = smask[(gb0 + blkl) * UU + tid];
    }

    // ---- zero-init input tile, stage x(0) ----
    {
        float4* inp4 = (float4*)inp;
        float4 z = make_float4(0.f, 0.f, 0.f, 0.f);
        for (int idx = tid; idx < BPG * NCH4; idx += NTHR)
            inp4[idx / NCH4 * NCH4 + (idx % NCH4)] = z;
        __syncthreads();
        if (tid < BPG) {
            const float* xp = strokes + (size_t)(gb0 + tid) * TT * 3;
            inp4[tid * NCH4 + 20] = make_float4(xp[0], xp[1], xp[2], 0.f);
        }
    }

    // GEMM mapping: 4b x 4j per-thread tile, k split across 8 threads
    const int ks      = tid & 7;
    const int cluster = tid >> 3;           // 0..63
    const int b0 = (cluster & 3) * 4;       // batch tile (of 16)
    const int j0 = (cluster >> 2) * 4;      // gate-row tile (of 64)
    // cell-update mapping (threads 0..255): one (batch, col) each
    const int lb  = tid >> 4;               // local batch 0..15
    const int col = tid & 15;               // local h column 0..15
    float c_state = 0.0f;

    const float4* w0 = (const float4*)(Wsh + (j0 + 0) * KP);
    const float4* w1 = (const float4*)(Wsh + (j0 + 1) * KP);
    const float4* w2 = (const float4*)(Wsh + (j0 + 2) * KP);
    const float4* w3 = (const float4*)(Wsh + (j0 + 3) * KP);
    const float4* i0 = (const float4*)(inp + (b0 + 0) * KP);
    const float4* i1 = (const float4*)(inp + (b0 + 1) * KP);
    const float4* i2 = (const float4*)(inp + (b0 + 2) * KP);
    const float4* i3 = (const float4*)(inp + (b0 + 3) * KP);

    float acc[4][4];
    #pragma unroll
    for (int i = 0; i < 4; ++i)
        #pragma unroll
        for (int j = 0; j < 4; ++j) acc[i][j] = 0.0f;

    __syncthreads();

    // ---- pre-loop partial GEMM: x(0) + h(-1)=0 contribution ----
    #pragma unroll 2
    for (int c = 20 + ks; c < NCH4; c += 8) {
        float4 wv[4], iv[4];
        wv[0] = w0[c]; wv[1] = w1[c]; wv[2] = w2[c]; wv[3] = w3[c];
        iv[0] = i0[c]; iv[1] = i1[c]; iv[2] = i2[c]; iv[3] = i3[c];
        #pragma unroll
        for (int i = 0; i < 4; ++i)
            #pragma unroll
            for (int j = 0; j < 4; ++j) {
                acc[i][j] = fmaf(iv[i].x, wv[j].x, acc[i][j]);
                acc[i][j] = fmaf(iv[i].y, wv[j].y, acc[i][j]);
                acc[i][j] = fmaf(iv[i].z, wv[j].z, acc[i][j]);
                acc[i][j] = fmaf(iv[i].w, wv[j].w, acc[i][j]);
            }
    }

    for (int t = 0; t < TT; ++t) {
        // ======== stage w(t-1) (20 chunks per batch) ========
        if (t > 0) {
            float4* inp4 = (float4*)inp;
            for (int idx = tid; idx < BPG * 20; idx += NTHR) {
                int b = idx / 20;
                int c = idx - b * 20;
                inp4[b * NCH4 + c] =
                    __ldcg((const float4*)(ws_out + ((size_t)(gb0 + b) * TT + (t - 1)) * NC + c * 4));
            }
        }
        __syncthreads();

        // ======== w-part GEMM: chunks [0,20) ========
        {
            #pragma unroll 1
            for (int c = ks; c < 20; c += 8) {
                float4 wv[4], iv[4];
                wv[0] = w0[c]; wv[1] = w1[c]; wv[2] = w2[c]; wv[3] = w3[c];
                iv[0] = i0[c]; iv[1] = i1[c]; iv[2] = i2[c]; iv[3] = i3[c];
                #pragma unroll
                for (int i = 0; i < 4; ++i)
                    #pragma unroll
                    for (int j = 0; j < 4; ++j) {
                        acc[i][j] = fmaf(iv[i].x, wv[j].x, acc[i][j]);
                        acc[i][j] = fmaf(iv[i].y, wv[j].y, acc[i][j]);
                        acc[i][j] = fmaf(iv[i].z, wv[j].z, acc[i][j]);
                        acc[i][j] = fmaf(iv[i].w, wv[j].w, acc[i][j]);
                    }
            }
            // reduce over the 8 k-split lanes (tid bits 0..2)
            #pragma unroll
            for (int i = 0; i < 4; ++i)
                #pragma unroll
                for (int j = 0; j < 4; ++j) {
                    float a = acc[i][j];
                    a += __shfl_xor_sync(0xffffffffu, a, 1);
                    a += __shfl_xor_sync(0xffffffffu, a, 2);
                    a += __shfl_xor_sync(0xffffffffu, a, 4);
                    if (ks == 0) gbuf[(j0 + j) * GSTR + (b0 + i)] = a;
                    acc[i][j] = 0.0f;              // reset for next step's partial
                }
        }
        __syncthreads();

        // ======== LSTM cell update (threads 0..255) ========
        if (tid < 256) {
            float gi = gbuf[(0 * 16 + col) * GSTR + lb] + bias_sh[col];
            float gf = gbuf[(1 * 16 + col) * GSTR + lb] + bias_sh[16 + col];
            float gg = gbuf[(2 * 16 + col) * GSTR + lb] + bias_sh[32 + col];
            float go = gbuf[(3 * 16 + col) * GSTR + lb] + bias_sh[48 + col];
            float si = sigmoidf_acc(gi);
            float sf = sigmoidf_acc(gf);
            float so = sigmoidf_acc(go);
            c_state = sf * c_state + si * tanhf(gg);
            float h = so * tanhf(c_state);
            hs_out[((size_t)(gb0 + lb) * TT + t) * HH + hc0 + col] = h;
        }

        group_sync(grp);   // h(t) of this group's 16 batches fully visible

        // ======== stage h(t) + x(t+1) (group's batches only: 32KB) ========
        {
            float4* inp4 = (float4*)inp;
            #pragma unroll 4
            for (int idx = tid; idx < BPG * 128; idx += NTHR) {
                int b = idx >> 7;
                int c = idx & 127;
                inp4[b * NCH4 + HCH0 + c] =
                    __ldcg((const float4*)(hs_out + ((size_t)(gb0 + b) * TT + t) * HH + c * 4));
            }
            if (tid < BPG) {
                int tn = (t + 1 < TT) ? (t + 1) : (TT - 1);
                const float* xp = strokes + ((size_t)(gb0 + tid) * TT + tn) * 3;
                inp4[tid * NCH4 + 20] = make_float4(xp[0], xp[1], xp[2], 0.f);
            }
        }
        __syncthreads();

        // ======== window (blocks 0..15 of group; batch gb0+blkl) ========
        if (blkl < BPG) {
            const float* hrow = inp + blkl * KP + HOFF;   // staged h(t)[batch]

            // p[30] = h @ W_win.T + b_win (16 threads per output)
            {
                int j = tid >> 4;
                int seg = tid & 15;
                float part = 0.0f;
                if (j < 30) {
                    const float4* wr = (const float4*)(W_win + j * HH + seg * 32);
                    const float4* hr = (const float4*)(hrow + seg * 32);
                    #pragma unroll
                    for (int m = 0; m < 8; ++m) {
                        float4 wv = wr[m];
                        float4 hv = hr[m];
                        part = fmaf(hv.x, wv.x, part);
                        part = fmaf(hv.y, wv.y, part);
                        part = fmaf(hv.z, wv.z, part);
                        part = fmaf(hv.w, wv.w, part);
                    }
                }
                part += __shfl_down_sync(0xffffffffu, part, 8, 16);
                part += __shfl_down_sync(0xffffffffu, part, 4, 16);
                part += __shfl_down_sync(0xffffffffu, part, 2, 16);
                part += __shfl_down_sync(0xffffffffu, part, 1, 16);
                if (seg == 0 && j < 30) psh[j] = part + b_win[j];
            }
            __syncthreads();

            if (tid < KG) {
                alpha_sh[tid] = expf(psh[tid]);
                beta_sh[tid]  = expf(psh[10 + tid]);
                kap_sh[tid]  += expf(psh[20 + tid]);   // persistent kappa
            }
            __syncthreads();

            if (tid < UU) {
                float uu = (float)tid;
                float ph = 0.0f;
                #pragma unroll
                for (int k = 0; k < KG; ++k) {
                    float d = kap_sh[k] - uu;
                    ph += alpha_sh[k] * expf(-beta_sh[k] * d * d);
                }
                phi_sh[tid] = ph * msh[tid];
            }
            __syncthreads();

            if (tid < NC) {
                float a = 0.0f;
                #pragma unroll 8
                for (int u = 0; u < UU; ++u)
                    a += (ssh[u] == tid) ? phi_sh[u] : 0.0f;
                ws_out[((size_t)(gb0 + blkl) * TT + t) * NC + tid] = a;
            }
        }

        // ======== partial GEMM for step t+1: chunks [20,153) (h + x) ========
        #pragma unroll 2
        for (int c = 20 + ks; c < NCH4; c += 8) {
            float4 wv[4], iv[4];
            wv[0] = w0[c]; wv[1] = w1[c]; wv[2] = w2[c]; wv[3] = w3[c];
            iv[0] = i0[c]; iv[1] = i1[c]; iv[2] = i2[c]; iv[3] = i3[c];
            #pragma unroll
            for (int i = 0; i < 4; ++i)
                #pragma unroll
                for (int j = 0; j < 4; ++j) {
                    acc[i][j] = fmaf(iv[i].x, wv[j].x, acc[i][j]);
                    acc[i][j] = fmaf(iv[i].y, wv[j].y, acc[i][j]);
                    acc[i][j] = fmaf(iv[i].z, wv[j].z, acc[i][j]);
                    acc[i][j] = fmaf(iv[i].w, wv[j].w, acc[i][j]);
                }
        }

        group_sync(grp);   // w(t) visible for step t+1
    }
}

// ---------------- launch ----------------
extern "C" void kernel_launch(void* const* d_in, const int* in_sizes, int n_in,
                              void* d_out, int out_size) {
    const float* strokes = (const float*)d_in[0];
    const int*   sents   = (const int*)  d_in[1];
    const float* smaskp  = (const float*)d_in[2];
    const float* W_ih    = (const float*)d_in[3];
    const float* W_hh    = (const float*)d_in[4];
    const float* b_ih    = (const float*)d_in[5];
    const float* b_hh    = (const float*)d_in[6];
    const float* W_win   = (const float*)d_in[7];
    const float* b_win   = (const float*)d_in[8];
    float* out = (float*)d_out;

    cudaFuncSetAttribute(lstm_attn_kernel,
                         cudaFuncAttributeMaxDynamicSharedMemorySize, SMEM_BYTES);

    lstm_attn_kernel<<<NBLK, NTHR, SMEM_BYTES>>>(
        strokes, sents, smaskp, W_ih, W_hh, b_ih, b_hh, W_win, b_win, out);
}

// round 4
// speedup vs baseline: 1.8342x; 1.0718x over previous
#include <cuda_runtime.h>
#include <math.h>

// Problem constants
#define BB   64
#define TT   512
#define HH   512
#define KG   10
#define NC   80
#define UU   64

#define NBLK 128
#define NTHR 512
#define NGRP 4
#define GBLK 32      // blocks per group
#define BPG  16      // batches per group
#define RPB  64      // gate rows per block (16 h-cols x 4 gates)
#define CPB  16      // h columns per block

// padded K dimension of the fused recurrent GEMM:
//  [0,80)   : w  (W_ih cols 3..83)
//  [80,83)  : x  (W_ih cols 0..3)
//  [83]     : zero pad
//  [84,596) : h  (W_hh cols 0..512)
//  [596,612): zero pad
#define KP    612
#define NCH4  153     // KP/4 float4 chunks per row
#define HOFF  84
#define HCH0  21      // first float4 chunk of h region
#define GSTR  17      // gbuf row stride (16 batches + pad)

#define SMEM_FLOATS (RPB*KP + BPG*KP + RPB*GSTR)
#define SMEM_BYTES  (SMEM_FLOATS * 4)

// ---------------- per-group sync primitives ----------------
__device__ unsigned g_bar_count[NGRP] = {0, 0, 0, 0};
__device__ volatile unsigned g_bar_gen[NGRP] = {0, 0, 0, 0};
__device__ unsigned g_w_cnt[NGRP] = {0, 0, 0, 0};   // w(t) publication counter

__device__ __forceinline__ void group_sync(int grp) {
    __threadfence();
    __syncthreads();
    if (threadIdx.x == 0) {
        unsigned gen = g_bar_gen[grp];
        if (atomicAdd(&g_bar_count[grp], 1u) == (unsigned)(GBLK - 1)) {
            g_bar_count[grp] = 0;
            __threadfence();
            g_bar_gen[grp] = gen + 1;
        } else {
            while (g_bar_gen[grp] == gen) { }
            __threadfence();
        }
    }
    __syncthreads();
}

__device__ __forceinline__ float fsig(float x) {
    return __fdividef(1.0f, 1.0f + __expf(-x));
}
__device__ __forceinline__ float ftanh(float x) {
    x = fminf(fmaxf(x, -15.0f), 15.0f);
    float e = __expf(2.0f * x);
    return __fdividef(e - 1.0f, e + 1.0f);
}

// ---------------- persistent kernel ----------------
__global__ __launch_bounds__(NTHR, 1)
void lstm_attn_kernel(const float* __restrict__ strokes,   // [B,T,3]
                      const int*   __restrict__ sents,     // [B,U]
                      const float* __restrict__ smask,     // [B,U]
                      const float* __restrict__ W_ih,      // [2048,83]
                      const float* __restrict__ W_hh,      // [2048,512]
                      const float* __restrict__ b_ih,      // [2048]
                      const float* __restrict__ b_hh,      // [2048]
                      const float* __restrict__ W_win,     // [30,512]
                      const float* __restrict__ b_win,     // [30]
                      float* __restrict__ out)
{
    extern __shared__ float sm[];
    float* Wsh  = sm;                 // RPB * KP
    float* inp  = Wsh + RPB * KP;     // BPG * KP
    float* gbuf = inp + BPG * KP;     // RPB * GSTR

    __shared__ float bias_sh[RPB];
    __shared__ float psh[32];
    __shared__ float phi_sh[UU];
    __shared__ int   ssh[UU];
    __shared__ float msh[UU];

    const int tid  = threadIdx.x;
    const int blk  = blockIdx.x;
    const int grp  = blk >> 5;
    const int blkl = blk & 31;
    const int hc0  = blkl * CPB;
    const int gb0  = grp * BPG;

    float* hs_out = out;                               // [B,T,H]
    float* ws_out = out + (size_t)BB * TT * HH;        // [B,T,NC]

    // ---- load this block's 64-row weight slice into smem (once) ----
    for (int e = tid; e < RPB * KP; e += NTHR) {
        int j = e / KP;
        int k = e - j * KP;
        int row = (j >> 4) * HH + hc0 + (j & 15);
        float v = 0.0f;
        if (k < 80)                      v = W_ih[row * 83 + 3 + k];
        else if (k < 83)                 v = W_ih[row * 83 + (k - 80)];
        else if (k >= HOFF && k < HOFF + HH) v = W_hh[row * HH + (k - HOFF)];
        Wsh[e] = v;
    }
    if (tid < RPB) {
        int row = (tid >> 4) * HH + hc0 + (tid & 15);
        bias_sh[tid] = b_ih[row] + b_hh[row];
    }
    if (blkl < BPG && tid < UU) {
        ssh[tid] = sents[(gb0 + blkl) * UU + tid];
        msh[tid] = smask[(gb0 + blkl) * UU + tid];
    }

    // ---- zero-init input tile, stage x(0) ----
    {
        float4* inp4 = (float4*)inp;
        float4 z = make_float4(0.f, 0.f, 0.f, 0.f);
        for (int idx = tid; idx < BPG * NCH4; idx += NTHR)
            inp4[idx] = z;
        __syncthreads();
        if (tid < BPG) {
            const float* xp = strokes + (size_t)(gb0 + tid) * TT * 3;
            inp4[tid * NCH4 + 20] = make_float4(xp[0], xp[1], xp[2], 0.f);
        }
    }

    // GEMM mapping: 4b x 4j per-thread tile, k split across 8 threads
    const int ks      = tid & 7;
    const int cluster = tid >> 3;
    const int b0 = (cluster & 3) * 4;
    const int j0 = (cluster >> 2) * 4;
    // cell-update mapping (threads 0..255)
    const int lb  = tid >> 4;
    const int col = tid & 15;
    float c_state = 0.0f;
    float kappa_reg = 0.0f;     // warp0 lanes 0..9 of window blocks

    const float4* w0 = (const float4*)(Wsh + (j0 + 0) * KP);
    const float4* w1 = (const float4*)(Wsh + (j0 + 1) * KP);
    const float4* w2 = (const float4*)(Wsh + (j0 + 2) * KP);
    const float4* w3 = (const float4*)(Wsh + (j0 + 3) * KP);
    const float4* i0 = (const float4*)(inp + (b0 + 0) * KP);
    const float4* i1 = (const float4*)(inp + (b0 + 1) * KP);
    const float4* i2 = (const float4*)(inp + (b0 + 2) * KP);
    const float4* i3 = (const float4*)(inp + (b0 + 3) * KP);

    float acc[4][4];
    #pragma unroll
    for (int i = 0; i < 4; ++i)
        #pragma unroll
        for (int j = 0; j < 4; ++j) acc[i][j] = 0.0f;

    __syncthreads();

    // ---- pre-loop partial GEMM: x(0) contribution (h(-1)=0) ----
    #pragma unroll 2
    for (int c = 20 + ks; c < NCH4; c += 8) {
        float4 wv[4], iv[4];
        wv[0] = w0[c]; wv[1] = w1[c]; wv[2] = w2[c]; wv[3] = w3[c];
        iv[0] = i0[c]; iv[1] = i1[c]; iv[2] = i2[c]; iv[3] = i3[c];
        #pragma unroll
        for (int i = 0; i < 4; ++i)
            #pragma unroll
            for (int j = 0; j < 4; ++j) {
                acc[i][j] = fmaf(iv[i].x, wv[j].x, acc[i][j]);
                acc[i][j] = fmaf(iv[i].y, wv[j].y, acc[i][j]);
                acc[i][j] = fmaf(iv[i].z, wv[j].z, acc[i][j]);
                acc[i][j] = fmaf(iv[i].w, wv[j].w, acc[i][j]);
            }
    }

    for (int t = 0; t < TT; ++t) {
        // ======== wait for + stage w(t-1) ========
        if (t > 0) {
            if (tid == 0) {
                unsigned need = 16u * (unsigned)t;
                while (*(volatile const unsigned*)&g_w_cnt[grp] < need) { }
                __threadfence();
            }
            __syncthreads();
            float4* inp4 = (float4*)inp;
            for (int idx = tid; idx < BPG * 20; idx += NTHR) {
                int b = idx / 20;
                int c = idx - b * 20;
                inp4[b * NCH4 + c] =
                    __ldcg((const float4*)(ws_out + ((size_t)(gb0 + b) * TT + (t - 1)) * NC + c * 4));
            }
        }
        __syncthreads();

        // ======== w-part GEMM: chunks [0,20) ========
        {
            #pragma unroll 1
            for (int c = ks; c < 20; c += 8) {
                float4 wv[4], iv[4];
                wv[0] = w0[c]; wv[1] = w1[c]; wv[2] = w2[c]; wv[3] = w3[c];
                iv[0] = i0[c]; iv[1] = i1[c]; iv[2] = i2[c]; iv[3] = i3[c];
                #pragma unroll
                for (int i = 0; i < 4; ++i)
                    #pragma unroll
                    for (int j = 0; j < 4; ++j) {
                        acc[i][j] = fmaf(iv[i].x, wv[j].x, acc[i][j]);
                        acc[i][j] = fmaf(iv[i].y, wv[j].y, acc[i][j]);
                        acc[i][j] = fmaf(iv[i].z, wv[j].z, acc[i][j]);
                        acc[i][j] = fmaf(iv[i].w, wv[j].w, acc[i][j]);
                    }
            }
            #pragma unroll
            for (int i = 0; i < 4; ++i)
                #pragma unroll
                for (int j = 0; j < 4; ++j) {
                    float a = acc[i][j];
                    a += __shfl_xor_sync(0xffffffffu, a, 1);
                    a += __shfl_xor_sync(0xffffffffu, a, 2);
                    a += __shfl_xor_sync(0xffffffffu, a, 4);
                    if (ks == 0) gbuf[(j0 + j) * GSTR + (b0 + i)] = a;
                    acc[i][j] = 0.0f;
                }
        }
        __syncthreads();

        // ======== LSTM cell update (threads 0..255) ========
        if (tid < 256) {
            float gi = gbuf[(0 * 16 + col) * GSTR + lb] + bias_sh[col];
            float gf = gbuf[(1 * 16 + col) * GSTR + lb] + bias_sh[16 + col];
            float gg = gbuf[(2 * 16 + col) * GSTR + lb] + bias_sh[32 + col];
            float go = gbuf[(3 * 16 + col) * GSTR + lb] + bias_sh[48 + col];
            c_state = fsig(gf) * c_state + fsig(gi) * ftanh(gg);
            float h = fsig(go) * ftanh(c_state);
            hs_out[((size_t)(gb0 + lb) * TT + t) * HH + hc0 + col] = h;
        }

        group_sync(grp);   // h(t) of this group's 16 batches fully visible

        // ======== stage h(t) + x(t+1) ========
        {
            float4* inp4 = (float4*)inp;
            #pragma unroll 4
            for (int idx = tid; idx < BPG * 128; idx += NTHR) {
                int b = idx >> 7;
                int c = idx & 127;
                inp4[b * NCH4 + HCH0 + c] =
                    __ldcg((const float4*)(hs_out + ((size_t)(gb0 + b) * TT + t) * HH + c * 4));
            }
            if (tid < BPG) {
                int tn = (t + 1 < TT) ? (t + 1) : (TT - 1);
                const float* xp = strokes + ((size_t)(gb0 + tid) * TT + tn) * 3;
                inp4[tid * NCH4 + 20] = make_float4(xp[0], xp[1], xp[2], 0.f);
            }
        }
        __syncthreads();

        // ======== window (blocks 0..15 of group): p by all warps, rest by warp 0 ========
        if (blkl < BPG) {
            const float* hrow = inp + blkl * KP + HOFF;   // staged h(t)[batch]
            {
                int j = tid >> 4;
                int seg = tid & 15;
                float part = 0.0f;
                if (j < 30) {
                    const float4* wr = (const float4*)(W_win + j * HH + seg * 32);
                    const float4* hr = (const float4*)(hrow + seg * 32);
                    #pragma unroll
                    for (int m = 0; m < 8; ++m) {
                        float4 wv = wr[m];
                        float4 hv = hr[m];
                        part = fmaf(hv.x, wv.x, part);
                        part = fmaf(hv.y, wv.y, part);
                        part = fmaf(hv.z, wv.z, part);
                        part = fmaf(hv.w, wv.w, part);
                    }
                }
                part += __shfl_down_sync(0xffffffffu, part, 8, 16);
                part += __shfl_down_sync(0xffffffffu, part, 4, 16);
                part += __shfl_down_sync(0xffffffffu, part, 2, 16);
                part += __shfl_down_sync(0xffffffffu, part, 1, 16);
                if (seg == 0 && j < 30) psh[j] = part + b_win[j];
            }
            __syncthreads();

            if (tid < 32) {   // warp 0 solo; warps 1..15 proceed to pGEMM
                const int lane = tid;
                float al = 0.f, be = 0.f;
                if (lane < KG) {
                    al = __expf(psh[lane]);
                    be = __expf(psh[10 + lane]);
                    kappa_reg += __expf(psh[20 + lane]);
                }
                float u0 = (float)lane, u1 = (float)(lane + 32);
                float ph0 = 0.f, ph1 = 0.f;
                #pragma unroll
                for (int k = 0; k < KG; ++k) {
                    float av = __shfl_sync(0xffffffffu, al, k);
                    float bv = __shfl_sync(0xffffffffu, be, k);
                    float kv = __shfl_sync(0xffffffffu, kappa_reg, k);
                    float d0 = kv - u0;
                    float d1 = kv - u1;
                    ph0 = fmaf(av, __expf(-bv * d0 * d0), ph0);
                    ph1 = fmaf(av, __expf(-bv * d1 * d1), ph1);
                }
                phi_sh[lane]      = ph0 * msh[lane];
                phi_sh[lane + 32] = ph1 * msh[lane + 32];
                __syncwarp();

                float wa0 = 0.f, wa1 = 0.f, wa2 = 0.f;
                int n0 = lane, n1 = lane + 32, n2 = lane + 64;
                #pragma unroll 8
                for (int u = 0; u < UU; ++u) {
                    int   s  = ssh[u];
                    float pv = phi_sh[u];
                    wa0 += (s == n0) ? pv : 0.f;
                    wa1 += (s == n1) ? pv : 0.f;
                    wa2 += (s == n2) ? pv : 0.f;
                }
                float* wout = ws_out + ((size_t)(gb0 + blkl) * TT + t) * NC;
                wout[n0] = wa0;
                wout[n1] = wa1;
                if (lane < 16) wout[n2] = wa2;
                __threadfence();
                if (lane == 0) atomicAdd(&g_w_cnt[grp], 1u);
            }
        }

        // ======== partial GEMM for step t+1: chunks [20,153) (h + x) ========
        #pragma unroll 2
        for (int c = 20 + ks; c < NCH4; c += 8) {
            float4 wv[4], iv[4];
            wv[0] = w0[c]; wv[1] = w1[c]; wv[2] = w2[c]; wv[3] = w3[c];
            iv[0] = i0[c]; iv[1] = i1[c]; iv[2] = i2[c]; iv[3] = i3[c];
            #pragma unroll
            for (int i = 0; i < 4; ++i)
                #pragma unroll
                for (int j = 0; j < 4; ++j) {
                    acc[i][j] = fmaf(iv[i].x, wv[j].x, acc[i][j]);
                    acc[i][j] = fmaf(iv[i].y, wv[j].y, acc[i][j]);
                    acc[i][j] = fmaf(iv[i].z, wv[j].z, acc[i][j]);
                    acc[i][j] = fmaf(iv[i].w, wv[j].w, acc[i][j]);
                }
        }
        // no end-of-step barrier: w(t) consumers spin on g_w_cnt
    }

    // drain + reset the w counter for graph-replay determinism
    group_sync(grp);
    if (blkl == 0 && tid == 0) g_w_cnt[grp] = 0;
}

// ---------------- launch ----------------
extern "C" void kernel_launch(void* const* d_in, const int* in_sizes, int n_in,
                              void* d_out, int out_size) {
    const float* strokes = (const float*)d_in[0];
    const int*   sents   = (const int*)  d_in[1];
    const float* smaskp  = (const float*)d_in[2];
    const float* W_ih    = (const float*)d_in[3];
    const float* W_hh    = (const float*)d_in[4];
    const float* b_ih    = (const float*)d_in[5];
    const float* b_hh    = (const float*)d_in[6];
    const float* W_win   = (const float*)d_in[7];
    const float* b_win   = (const float*)d_in[8];
    float* out = (float*)d_out;

    cudaFuncSetAttribute(lstm_attn_kernel,
                         cudaFuncAttributeMaxDynamicSharedMemorySize, SMEM_BYTES);

    lstm_attn_kernel<<<NBLK, NTHR, SMEM_BYTES>>>(
        strokes, sents, smaskp, W_ih, W_hh, b_ih, b_hh, W_win, b_win, out);
}